// round 16
// baseline (speedup 1.0000x reference)
#include <cuda_runtime.h>
#include <math.h>
#include <stdint.h>

#define BATCH 128
#define HID   512
#define ATT   128
#define TT    256
#define CC    256
#define NEG_SLOPE 0.01f
#define NBLK  128
#define NTHR  1024

// pre-split packed-bf16 weight buffer layout (u32 = bf16x2; offsets in f32 units)
#define W1OFF 0
#define W1LD  1152
#define W2OFF (2048 * 1152)
#define W2LD  1024
#define W3OFF (W2OFF + 2048 * 1024)
#define W3LD  1024
#define WMOFF (W3OFF + 2048 * 1024)
#define WMLD  640
#define WTOT  (WMOFF + 512 * 640)
#define WTOT2 (WTOT / 2)

// -------------------- device-global scratch (no allocs allowed) ----------------
__device__ float g_h1[BATCH * HID];
__device__ float g_c1[BATCH * HID];
__device__ float g_h2[BATCH * HID];
__device__ float g_c2[BATCH * HID];
__device__ float g_h3[BATCH * HID];
__device__ float g_c3[BATCH * HID];
__device__ float g_ctx[BATCH * ATT];
__device__ float g_part[8 * BATCH * 2048];   // split-K partials, gate GEMMs
__device__ float g_mpart[8 * BATCH * HID];   // split-K partials, mlp GEMM
__device__ unsigned g_wh[WTOT2];             // bf16x2-packed hi weights
__device__ unsigned g_wl[WTOT2];             // bf16x2-packed lo weights
__device__ unsigned g_ctr;                   // barrier arrivals (monotonic)
__device__ unsigned g_epoch;                 // released epochs (monotonic)

// -------------------- shared memory ----------------------------------------------
struct GemmSmem  { unsigned ah[2048]; unsigned al[2048]; unsigned wh[2048]; unsigned wl[2048]; };
struct AttSmem   { float hs[HID]; float pr[NTHR]; float qs[ATT]; float at[TT]; float red[32]; };
struct Proj4Smem { float ms[4][512]; float lg[4][256]; float red[64]; };
union SmemAll { GemmSmem g; AttSmem a; Proj4Smem p4; };
#define SMEM_BYTES (sizeof(SmemAll) + 1024)

// -------------------- fast activations ----------------------------------------------
__device__ __forceinline__ float sigm_f(float x) {
    return __fdividef(1.f, 1.f + __expf(-x));
}
__device__ __forceinline__ float tanh_f(float x) {
    return 2.f * __fdividef(1.f, 1.f + __expf(-2.f * x)) - 1.f;
}

// -------------------- bf16 helpers --------------------------------------------------
__device__ __forceinline__ unsigned pbf2(float lo, float hi) {
    unsigned r;
    asm("cvt.rn.bf16x2.f32 %0, %1, %2;" : "=r"(r) : "f"(hi), "f"(lo));
    return r;
}
__device__ __forceinline__ float bflo(unsigned u) { return __uint_as_float(u << 16); }
__device__ __forceinline__ float bfhi(unsigned u) { return __uint_as_float(u & 0xffff0000u); }

// m16n8k16 bf16 mma: D += A x B (fp32 accumulate)
__device__ __forceinline__ void mma16(float* d, const uint32_t* a, const uint32_t* b) {
    asm volatile(
        "mma.sync.aligned.m16n8k16.row.col.f32.bf16.bf16.f32 "
        "{%0,%1,%2,%3}, {%4,%5,%6,%7}, {%8,%9}, {%0,%1,%2,%3};"
        : "+f"(d[0]), "+f"(d[1]), "+f"(d[2]), "+f"(d[3])
        : "r"(a[0]), "r"(a[1]), "r"(a[2]), "r"(a[3]), "r"(b[0]), "r"(b[1]));
}

// packed-u32 smem index: row m (0..127), u32-col c (0..15)
__device__ __forceinline__ int swz2(int m, int c) {
    return (m << 4) + ((c + (((m >> 1) & 3) << 2)) & 15);
}

// -------------------- grid barrier (single counter + epoch, tight poll) -------------
__device__ __forceinline__ void st_rel(unsigned* p, unsigned v) {
    asm volatile("st.release.gpu.u32 [%0], %1;" :: "l"(p), "r"(v) : "memory");
}
__device__ __forceinline__ unsigned ld_acq(const unsigned* p) {
    unsigned v;
    asm volatile("ld.acquire.gpu.u32 %0, [%1];" : "=r"(v) : "l"(p) : "memory");
    return v;
}
__device__ __forceinline__ void gbar(unsigned goal) {   // goal = absolute epoch
    __syncthreads();
    if (threadIdx.x == 0) {
        unsigned v;
        asm volatile("atom.add.acq_rel.gpu.u32 %0, [%1], %2;"
                     : "=r"(v) : "l"(&g_ctr), "r"(1u) : "memory");
        if (v + 1 == goal * NBLK) st_rel(&g_epoch, goal);
        while (ld_acq(&g_epoch) < goal) { }   // tight poll
    }
    __syncthreads();
}

// -------------------- reductions (1024 threads = 32 warps) ---------------------------
__device__ __forceinline__ float warpMax(float v) {
    #pragma unroll
    for (int o = 16; o; o >>= 1) v = fmaxf(v, __shfl_xor_sync(0xffffffffu, v, o));
    return v;
}
__device__ __forceinline__ float warpSum(float v) {
    #pragma unroll
    for (int o = 16; o; o >>= 1) v += __shfl_xor_sync(0xffffffffu, v, o);
    return v;
}
__device__ float blockMax(float v, float* red) {
    v = warpMax(v);
    if ((threadIdx.x & 31) == 0) red[threadIdx.x >> 5] = v;
    __syncthreads();
    if (threadIdx.x < 32) {
        float x = red[threadIdx.x];
        x = warpMax(x);
        if (threadIdx.x == 0) red[0] = x;
    }
    __syncthreads();
    float r = red[0];
    __syncthreads();
    return r;
}
__device__ float blockSum(float v, float* red) {
    v = warpSum(v);
    if ((threadIdx.x & 31) == 0) red[threadIdx.x >> 5] = v;
    __syncthreads();
    if (threadIdx.x < 32) {
        float x = red[threadIdx.x];
        x = warpSum(x);
        if (threadIdx.x == 0) red[0] = x;
    }
    __syncthreads();
    float r = red[0];
    __syncthreads();
    return r;
}

// -------------------- one-time weight hi/lo split + bf16x2 pack ----------------------
__device__ void split_seg(size_t dbase, int dld, int dcol,
                          const float* __restrict__ src, int rows, int cols)
{
    const int gid = blockIdx.x * NTHR + threadIdx.x;
    const int total = (rows * cols) >> 2;
    const int c4 = cols >> 2;
    for (int i = gid; i < total; i += NBLK * NTHR) {
        const int r = i / c4;
        const int c = (i - r * c4) << 2;
        const float4 v = *reinterpret_cast<const float4*>(src + (size_t)r * cols + c);
        const unsigned h0 = pbf2(v.x, v.y);
        const unsigned h1 = pbf2(v.z, v.w);
        const unsigned l0 = pbf2(v.x - bflo(h0), v.y - bfhi(h0));
        const unsigned l1 = pbf2(v.z - bflo(h1), v.w - bfhi(h1));
        const size_t o2 = (dbase + (size_t)r * dld + dcol + c) >> 1;
        g_wh[o2] = h0; g_wh[o2 + 1] = h1;
        g_wl[o2] = l0; g_wl[o2 + 1] = l1;
    }
}

// -------------------- tensor-core GEMM job (3xBF16 m16n8k16, 8x4 warps) --------------
// staging on tid<512 (identical proven pattern); mma spread over 32 warps (16x32 each)
__device__ void gemm_mma(SmemAll& SS, int jid, int t,
    float* part, int partN, int ntN, int nchunks, int ksplit,
    const float* emb, const int* Yin, int ystride, int s0,
    const float* p1, int l1, int s1,
    const float* p2, int l2,
    size_t woff, int wld)
{
    if (jid < 0 || jid >= ntN * ksplit) return;
    unsigned* AH = SS.g.ah; unsigned* AL = SS.g.al;
    unsigned* WH = SS.g.wh; unsigned* WL = SS.g.wl;

    const int tid = threadIdx.x;
    const int nt = jid / ksplit, ks = jid % ksplit;
    const int N0 = nt * 128;
    const int q = nchunks / ksplit, r = nchunks % ksplit;
    const int cnt = q + (ks < r ? 1 : 0);
    const int c0 = ks * q + (ks < r ? ks : r);

    const bool stg = (tid < 512);
    const int lm  = tid & 127;
    const int lkg = ((tid >> 7) & 3) << 3;   // 0,8,16,24 for tid<512
    const int lane = tid & 31;
    const int wid = tid >> 5;                // 0..31
    const int wm = wid & 7;                  // 8 m-tiles of 16 rows
    const int wn = wid >> 3;                 // 4 n-tiles of 32 cols
    const int fr = lane >> 2;
    const int fc = lane & 3;

    const unsigned* wsh2 = g_wh + (woff >> 1) + (size_t)(N0 + lm) * (wld >> 1);
    const unsigned* wsl2 = g_wl + (woff >> 1) + (size_t)(N0 + lm) * (wld >> 1);

    float acc[4][4];
    #pragma unroll
    for (int j = 0; j < 4; j++)
        #pragma unroll
        for (int x = 0; x < 4; x++) acc[j][x] = 0.f;

    float4 ar0, ar1;
    uint4 w4h, w4l;

    #define LOADCHUNK(CK)                                                        \
        if (stg) {                                                               \
            const int gk = ((CK) << 5) + lkg;                                    \
            const float* ap;                                                     \
            if (gk < s0)      ap = emb + (size_t)Yin[lm * ystride + t] * HID + gk; \
            else if (gk < s1) ap = p1 + (size_t)lm * l1 + (gk - s0);             \
            else              ap = p2 + (size_t)lm * l2 + (gk - s1);             \
            ar0 = *reinterpret_cast<const float4*>(ap);                          \
            ar1 = *reinterpret_cast<const float4*>(ap + 4);                      \
            w4h = *reinterpret_cast<const uint4*>(wsh2 + (gk >> 1));             \
            w4l = *reinterpret_cast<const uint4*>(wsl2 + (gk >> 1));             \
        }

    LOADCHUNK(c0);

    const int c0u = ((tid >> 7) & 3) << 2;
    const int dstg = (lm << 4) + ((c0u + (((lm >> 1) & 3) << 2)) & 15);

    for (int cc = 0; cc < cnt; cc++) {
        __syncthreads();
        if (stg) {
            const unsigned h0 = pbf2(ar0.x, ar0.y);
            const unsigned h1 = pbf2(ar0.z, ar0.w);
            const unsigned h2 = pbf2(ar1.x, ar1.y);
            const unsigned h3 = pbf2(ar1.z, ar1.w);
            const unsigned l0 = pbf2(ar0.x - bflo(h0), ar0.y - bfhi(h0));
            const unsigned l1 = pbf2(ar0.z - bflo(h1), ar0.w - bfhi(h1));
            const unsigned l2r = pbf2(ar1.x - bflo(h2), ar1.y - bfhi(h2));
            const unsigned l3 = pbf2(ar1.z - bflo(h3), ar1.w - bfhi(h3));
            *reinterpret_cast<uint4*>(AH + dstg) = make_uint4(h0, h1, h2, h3);
            *reinterpret_cast<uint4*>(AL + dstg) = make_uint4(l0, l1, l2r, l3);
            *reinterpret_cast<uint4*>(WH + dstg) = w4h;
            *reinterpret_cast<uint4*>(WL + dstg) = w4l;
        }
        __syncthreads();

        if (cc + 1 < cnt) LOADCHUNK(c0 + cc + 1);

        #pragma unroll
        for (int ks2 = 0; ks2 < 2; ks2++) {
            const int kb2 = ks2 << 3;
            const int ra = 16 * wm + fr;
            uint32_t ah[4], al[4];
            ah[0] = AH[swz2(ra,     kb2 + fc)];
            ah[1] = AH[swz2(ra + 8, kb2 + fc)];
            ah[2] = AH[swz2(ra,     kb2 + fc + 4)];
            ah[3] = AH[swz2(ra + 8, kb2 + fc + 4)];
            al[0] = AL[swz2(ra,     kb2 + fc)];
            al[1] = AL[swz2(ra + 8, kb2 + fc)];
            al[2] = AL[swz2(ra,     kb2 + fc + 4)];
            al[3] = AL[swz2(ra + 8, kb2 + fc + 4)];
            #pragma unroll
            for (int j = 0; j < 4; j++) {
                const int nb = 32 * wn + 8 * j + fr;
                uint32_t bh[2], bl[2];
                bh[0] = WH[swz2(nb, kb2 + fc)];
                bh[1] = WH[swz2(nb, kb2 + fc + 4)];
                bl[0] = WL[swz2(nb, kb2 + fc)];
                bl[1] = WL[swz2(nb, kb2 + fc + 4)];
                mma16(acc[j], ah, bh);
                mma16(acc[j], ah, bl);
                mma16(acc[j], al, bh);
            }
        }
    }
    #undef LOADCHUNK

    // epilogue: write split-K partials (warp tile 16 rows x 32 cols)
    #pragma unroll
    for (int j = 0; j < 4; j++) {
        const int row0 = 16 * wm + fr;
        const int col = N0 + 32 * wn + 8 * j + 2 * fc;
        float* op0 = part + (size_t)(ks * BATCH + row0) * partN + col;
        float* op1 = part + (size_t)(ks * BATCH + row0 + 8) * partN + col;
        *reinterpret_cast<float2*>(op0) = make_float2(acc[j][0], acc[j][1]);
        *reinterpret_cast<float2*>(op1) = make_float2(acc[j][2], acc[j][3]);
    }
}

// -------------------- LSTM pointwise update (block = batch row) ---------------------
__device__ void update_phase(float* h, float* c, const float* bih, const float* bhh,
                             int nks)
{
    const int b = blockIdx.x;
    const int tid = threadIdx.x;
    if (tid >= 512) return;
    const int j = tid;
    float gi = bih[j] + bhh[j];
    float gf = bih[j + 512] + bhh[j + 512];
    float gg = bih[j + 1024] + bhh[j + 1024];
    float go = bih[j + 1536] + bhh[j + 1536];
    for (int ks = 0; ks < nks; ks++) {
        const float* pk = g_part + (size_t)(ks * BATCH + b) * 2048;
        gi += pk[j];
        gf += pk[j + 512];
        gg += pk[j + 1024];
        go += pk[j + 1536];
    }
    const float ig = sigm_f(gi);
    const float fg = sigm_f(gf);
    const float og = sigm_f(go);
    const float gv = tanh_f(gg);
    const int idx = b * HID + j;
    const float cn = fg * c[idx] + ig * gv;
    c[idx] = cn;
    h[idx] = og * tanh_f(cn);
}

// -------------------- fused (upd3 +) attention (block = batch row, 1024 thr) --------
__device__ void attend_phase(SmemAll& SS, const float* key, const float* value,
                             const int* flens, const float* Wq, const float* bq,
                             const float* bih3, const float* bhh3, int fuse)
{
    AttSmem& A = SS.a;
    const int b = blockIdx.x;
    const int tid = threadIdx.x;

    if (tid < 512) {
        if (fuse) {
            const int j = tid;
            float gi = bih3[j] + bhh3[j];
            float gf = bih3[j + 512] + bhh3[j + 512];
            float gg = bih3[j + 1024] + bhh3[j + 1024];
            float go = bih3[j + 1536] + bhh3[j + 1536];
            #pragma unroll
            for (int ks = 0; ks < 8; ks++) {
                const float* pk = g_part + (size_t)(ks * BATCH + b) * 2048;
                gi += pk[j];
                gf += pk[j + 512];
                gg += pk[j + 1024];
                go += pk[j + 1536];
            }
            const float ig = sigm_f(gi);
            const float fg = sigm_f(gf);
            const float og = sigm_f(go);
            const float gv = tanh_f(gg);
            const int idx = b * HID + j;
            const float cn = fg * g_c3[idx] + ig * gv;
            g_c3[idx] = cn;
            const float hn = og * tanh_f(cn);
            g_h3[idx] = hn;
            A.hs[j] = hn;
        } else {
            A.hs[tid] = g_h3[b * HID + tid];
        }
    }
    __syncthreads();

    // q = h3 @ Wq^T + bq : warp w -> outputs a = 4w..4w+3, lanes split k (coalesced)
    {
        const int w = tid >> 5, ln = tid & 31;
        #pragma unroll
        for (int i = 0; i < 4; i++) {
            const int a = (w << 2) + i;
            const float* wr = Wq + (size_t)a * HID;
            float s = 0.f;
            #pragma unroll
            for (int it = 0; it < 4; it++) {
                const int k = it * 128 + ln * 4;
                const float4 wv = *reinterpret_cast<const float4*>(wr + k);
                s += wv.x * A.hs[k] + wv.y * A.hs[k + 1]
                   + wv.z * A.hs[k + 2] + wv.w * A.hs[k + 3];
            }
            s = warpSum(s);
            if (ln == 0) A.qs[a] = s + bq[a];
        }
    }
    __syncthreads();

    // energy: 4 threads per position t (32 a each) — coalesced over tp
    {
        const int tp = tid & 255;
        const int qt = tid >> 8;
        const float* kp = key + (size_t)b * ATT * TT + tp;
        float e = 0.f;
        #pragma unroll 8
        for (int a = 0; a < 32; a++) e += A.qs[qt * 32 + a] * kp[(size_t)(qt * 32 + a) * TT];
        A.pr[tid] = e;
    }
    __syncthreads();

    const int flen = flens[b] >> 3;
    const float ev = (tid < 256)
        ? (A.pr[tid] + A.pr[tid + 256] + A.pr[tid + 512] + A.pr[tid + 768]) : -3.4e38f;
    const float mx = blockMax(ev, A.red);
    const float w2 = (tid < 256 && tid < flen) ? __expf(ev - mx) : 0.f;
    const float sm = blockSum(w2, A.red);
    if (tid < 256) A.at[tid] = w2 / sm;
    __syncthreads();

    // ctx = attn @ value : 8 threads per output v (coalesced over v)
    {
        const int v = tid & 127;
        const int p = tid >> 7;
        const float* vp = value + (size_t)b * TT * ATT + (size_t)(p * 32) * ATT + v;
        float cs = 0.f;
        #pragma unroll 8
        for (int t2 = 0; t2 < 32; t2++) cs += A.at[p * 32 + t2] * vp[(size_t)t2 * ATT];
        A.pr[tid] = cs;
    }
    __syncthreads();
    if (tid < ATT) {
        float s = 0.f;
        #pragma unroll
        for (int p = 0; p < 8; p++) s += A.pr[tid + p * 128];
        g_ctx[b * ATT + tid] = s;
    }
    __syncthreads();
}

// -------------------- proj: 4 batch rows per block (blocks 0..31), coalesced --------
__device__ void proj_phase4(SmemAll& SS, const float* emb, const float* bproj,
                            const float* bmlp, float* out, int t, int ml, int pb)
{
    Proj4Smem& P = SS.p4;
    const int tid = threadIdx.x;

    // combine mlp split-K partials + bias + LeakyReLU for rows 4pb..4pb+3
    for (int idx = tid; idx < 2048; idx += NTHR) {
        const int rr = idx >> 9, j = idx & 511;
        const int b = pb * 4 + rr;
        float s = bmlp[j];
        #pragma unroll
        for (int ks = 0; ks < 8; ks++)
            s += g_mpart[((size_t)(ks * BATCH) + b) * HID + j];
        P.ms[rr][j] = (s >= 0.f) ? s : NEG_SLOPE * s;
    }
    __syncthreads();

    // logits: warp w -> row rr = w>>3, 32 classes; lanes split k (coalesced LDG.128)
    {
        const int w = tid >> 5, ln = tid & 31;
        const int rr = w >> 3;
        const int cb = (w & 7) << 5;
        const float* mr = P.ms[rr];
        for (int j = 0; j < 32; j++) {
            const int c = cb + j;
            const float* er = emb + (size_t)c * HID;
            float s = 0.f;
            #pragma unroll
            for (int it = 0; it < 4; it++) {
                const int k = it * 128 + ln * 4;
                const float4 wv = *reinterpret_cast<const float4*>(er + k);
                s += wv.x * mr[k] + wv.y * mr[k + 1] + wv.z * mr[k + 2] + wv.w * mr[k + 3];
            }
            s = warpSum(s);
            if (ln == 0) P.lg[rr][c] = s + bproj[c];
        }
    }
    __syncthreads();

    // per-row log-softmax: 256 threads per row
    const int rr2 = tid >> 8;
    const int c2 = tid & 255;
    const int wq = (tid >> 5) & 7;
    const float v0 = P.lg[rr2][c2];
    float mx = warpMax(v0);
    if ((tid & 31) == 0) P.red[rr2 * 8 + wq] = mx;
    __syncthreads();
    mx = P.red[rr2 * 8];
    #pragma unroll
    for (int i = 1; i < 8; i++) mx = fmaxf(mx, P.red[rr2 * 8 + i]);
    float sm = warpSum(__expf(v0 - mx));
    if ((tid & 31) == 0) P.red[32 + rr2 * 8 + wq] = sm;
    __syncthreads();
    sm = 0.f;
    #pragma unroll
    for (int i = 0; i < 8; i++) sm += P.red[32 + rr2 * 8 + i];
    const float lsm = __logf(sm);
    const int b = pb * 4 + rr2;
    out[((size_t)b * ml + t) * CC + c2] = v0 - mx - lsm;
    __syncthreads();
}

// -------------------- persistent megakernel -----------------------------------------
__global__ __launch_bounds__(NTHR, 1) void mega_kernel(
    const float* key, const float* value, const int* Yin, const int* flens,
    const float* emb, const float* Wq, const float* bq,
    const float* Wih1, const float* Whh1, const float* bih1, const float* bhh1,
    const float* Wih2, const float* Whh2, const float* bih2, const float* bhh2,
    const float* Wih3, const float* Whh3, const float* bih3, const float* bhh3,
    const float* Wmlp, const float* bmlp, const float* bproj,
    const float* h00, const float* h01, const float* h02,
    const float* c00, const float* c01, const float* c02,
    float* out, int ml, int ystride)
{
    extern __shared__ char dyn_smem[];
    char* sb = (char*)((((uintptr_t)dyn_smem) + 1023) & ~(uintptr_t)1023);
    SmemAll& S = *reinterpret_cast<SmemAll*>(sb);

    const int tid = threadIdx.x;
    const int bid = blockIdx.x;
    const unsigned base = ld_acq(&g_epoch);   // monotonic across replays
    unsigned bn = 0;

    // ---- one-time (per launch) weight hi/lo bf16 pre-split ----
    split_seg(W1OFF, W1LD, 0,   Wih1, 2048, 640);
    split_seg(W1OFF, W1LD, 640, Whh1, 2048, 512);
    split_seg(W2OFF, W2LD, 0,   Wih2, 2048, 512);
    split_seg(W2OFF, W2LD, 512, Whh2, 2048, 512);
    split_seg(W3OFF, W3LD, 0,   Wih3, 2048, 512);
    split_seg(W3OFF, W3LD, 512, Whh3, 2048, 512);
    split_seg(WMOFF, WMLD, 0,   Wmlp, 512, 640);

    // init state (broadcast initial h/c)
    {
        const int idx = bid * 512 + (tid & 511);
        if (tid < 512) {
            const int j = idx & 511;
            g_h1[idx] = h00[j]; g_h2[idx] = h01[j]; g_h3[idx] = h02[j];
            g_c1[idx] = c00[j]; g_c2[idx] = c01[j]; g_c3[idx] = c02[j];
        }
    }
    gbar(base + ++bn);
    attend_phase(S, key, value, flens, Wq, bq, bih3, bhh3, 0);
    gbar(base + ++bn);

    for (int t = 0; t < ml; t++) {
        // P1: GEMM1(t) on blocks 0..95 (ksplit 6) || mlp(t-1) on blocks 96..127
        if (bid < 96) {
            gemm_mma(S, bid, t, g_part, 2048, 16, 36, 6,
                     emb, Yin, ystride, 512,
                     g_ctx, ATT, 640, g_h1, HID,
                     W1OFF, W1LD);
        } else if (t > 0) {
            gemm_mma(S, bid - 96, t, g_mpart, 512, 4, 20, 8,
                     nullptr, nullptr, 0, 0,
                     g_h3, HID, 512, g_ctx, ATT,
                     WMOFF, WMLD);
        }
        gbar(base + ++bn);

        // P2: upd1(t) on all blocks + coalesced proj4(t-1) on blocks 0..31
        update_phase(g_h1, g_c1, bih1, bhh1, 6);
        if (t > 0 && bid < 32)
            proj_phase4(S, emb, bproj, bmlp, out, t - 1, ml, bid);
        gbar(base + ++bn);

        // P3: LSTM2 gate GEMM: A = [h1 | h2], K=1024
        gemm_mma(S, bid, t, g_part, 2048, 16, 32, 8,
                 nullptr, nullptr, 0, 0,
                 g_h1, HID, 512, g_h2, HID,
                 W2OFF, W2LD);
        gbar(base + ++bn);

        // P4: upd2
        update_phase(g_h2, g_c2, bih2, bhh2, 8);
        gbar(base + ++bn);

        // P5: LSTM3 gate GEMM: A = [h2 | h3], K=1024
        gemm_mma(S, bid, t, g_part, 2048, 16, 32, 8,
                 nullptr, nullptr, 0, 0,
                 g_h2, HID, 512, g_h3, HID,
                 W3OFF, W3LD);
        gbar(base + ++bn);

        // P6: attend(t) with fused upd3
        attend_phase(S, key, value, flens, Wq, bq, bih3, bhh3, 1);
        gbar(base + ++bn);
    }

    // drain: mlp(ml-1) then proj(ml-1)
    if (bid >= 96) {
        gemm_mma(S, bid - 96, ml - 1, g_mpart, 512, 4, 20, 8,
                 nullptr, nullptr, 0, 0,
                 g_h3, HID, 512, g_ctx, ATT,
                 WMOFF, WMLD);
    }
    gbar(base + ++bn);
    if (bid < 32)
        proj_phase4(S, emb, bproj, bmlp, out, ml - 1, ml, bid);
}

// -------------------- launch ----------------------------------------------------------
extern "C" void kernel_launch(void* const* d_in, const int* in_sizes, int n_in,
                              void* d_out, int out_size)
{
    const float* key        = (const float*)d_in[0];
    const float* value      = (const float*)d_in[1];
    const int*   Yinput     = (const int*)d_in[2];
    const int*   frame_lens = (const int*)d_in[3];
    // d_in[4] = max_len scalar; derived from out_size instead
    const float* emb   = (const float*)d_in[5];
    const float* Wq    = (const float*)d_in[6];
    const float* bq    = (const float*)d_in[7];
    const float* Wih1  = (const float*)d_in[8];
    const float* Whh1  = (const float*)d_in[9];
    const float* bih1  = (const float*)d_in[10];
    const float* bhh1  = (const float*)d_in[11];
    const float* Wih2  = (const float*)d_in[12];
    const float* Whh2  = (const float*)d_in[13];
    const float* bih2  = (const float*)d_in[14];
    const float* bhh2  = (const float*)d_in[15];
    const float* Wih3  = (const float*)d_in[16];
    const float* Whh3  = (const float*)d_in[17];
    const float* bih3  = (const float*)d_in[18];
    const float* bhh3  = (const float*)d_in[19];
    const float* Wmlp  = (const float*)d_in[20];
    const float* bmlp  = (const float*)d_in[21];
    const float* bproj = (const float*)d_in[22];
    const float* h00 = (const float*)d_in[23];
    const float* h01 = (const float*)d_in[24];
    const float* h02 = (const float*)d_in[25];
    const float* c00 = (const float*)d_in[26];
    const float* c01 = (const float*)d_in[27];
    const float* c02 = (const float*)d_in[28];

    float* out = (float*)d_out;
    const int ml = out_size / (BATCH * CC);     // 300
    const int ystride = in_sizes[2] / BATCH;    // MAXLEN = 300

    cudaFuncSetAttribute(mega_kernel,
                         cudaFuncAttributeMaxDynamicSharedMemorySize, SMEM_BYTES);

    mega_kernel<<<NBLK, NTHR, SMEM_BYTES>>>(
        key, value, Yinput, frame_lens,
        emb, Wq, bq,
        Wih1, Whh1, bih1, bhh1,
        Wih2, Whh2, bih2, bhh2,
        Wih3, Whh3, bih3, bhh3,
        Wmlp, bmlp, bproj,
        h00, h01, h02, c00, c01, c02,
        out, ml, ystride);
}

// round 17
// speedup vs baseline: 1.1794x; 1.1794x over previous
#include <cuda_runtime.h>
#include <math.h>
#include <stdint.h>

#define BATCH 128
#define HID   512
#define ATT   128
#define TT    256
#define CC    256
#define NEG_SLOPE 0.01f
#define NBLK  128
#define NTHR  512

// pre-split packed-bf16 weight buffer layout (u32 = bf16x2; offsets in f32 units)
// W1 = [Wih1 cols 512..639 (ctx) | Whh1] -> K=640
#define W1OFF 0
#define W1LD  640
#define W2OFF (2048 * 640)
#define W2LD  1024
#define W3OFF (W2OFF + 2048 * 1024)
#define W3LD  1024
#define WMOFF (W3OFF + 2048 * 1024)
#define WMLD  640
#define WTOT  (WMOFF + 512 * 640)
#define WTOT2 (WTOT / 2)

// -------------------- device-global scratch (no allocs allowed) ----------------
__device__ float g_h1[BATCH * HID];
__device__ float g_c1[BATCH * HID];
__device__ float g_h2[BATCH * HID];
__device__ float g_c2[BATCH * HID];
__device__ float g_h3[BATCH * HID];
__device__ float g_c3[BATCH * HID];
__device__ float g_ctx[BATCH * ATT];
__device__ float g_part[8 * BATCH * 2048];   // split-K partials, gate GEMMs
__device__ float g_mpart[8 * BATCH * HID];   // split-K partials, mlp GEMM
__device__ float g_etab[CC * 2048];          // emb @ Wih1[:, :512]^T  (per-class gate bias)
__device__ unsigned g_wh[WTOT2];             // bf16x2-packed hi weights
__device__ unsigned g_wl[WTOT2];             // bf16x2-packed lo weights
__device__ unsigned g_ctr;                   // barrier arrivals (monotonic)
__device__ unsigned g_epoch;                 // released epochs (monotonic)

// -------------------- shared memory ----------------------------------------------
struct GemmSmem  { unsigned ah[2048]; unsigned al[2048]; unsigned wh[2048]; unsigned wl[2048]; };
struct AttSmem   { float hs[NTHR]; float pr[NTHR]; float qs[ATT]; float at[TT]; float red[16]; };
struct Proj4Smem { float ms[4][512]; float lg[4][256]; float red[32]; };
union SmemAll { GemmSmem g; AttSmem a; Proj4Smem p4; };
#define SMEM_BYTES (sizeof(SmemAll) + 1024)

// -------------------- fast activations ----------------------------------------------
__device__ __forceinline__ float sigm_f(float x) {
    return __fdividef(1.f, 1.f + __expf(-x));
}
__device__ __forceinline__ float tanh_f(float x) {
    return 2.f * __fdividef(1.f, 1.f + __expf(-2.f * x)) - 1.f;
}

// -------------------- bf16 helpers --------------------------------------------------
__device__ __forceinline__ unsigned pbf2(float lo, float hi) {
    unsigned r;
    asm("cvt.rn.bf16x2.f32 %0, %1, %2;" : "=r"(r) : "f"(hi), "f"(lo));
    return r;
}
__device__ __forceinline__ float bflo(unsigned u) { return __uint_as_float(u << 16); }
__device__ __forceinline__ float bfhi(unsigned u) { return __uint_as_float(u & 0xffff0000u); }

// m16n8k16 bf16 mma: D += A x B (fp32 accumulate)
__device__ __forceinline__ void mma16(float* d, const uint32_t* a, const uint32_t* b) {
    asm volatile(
        "mma.sync.aligned.m16n8k16.row.col.f32.bf16.bf16.f32 "
        "{%0,%1,%2,%3}, {%4,%5,%6,%7}, {%8,%9}, {%0,%1,%2,%3};"
        : "+f"(d[0]), "+f"(d[1]), "+f"(d[2]), "+f"(d[3])
        : "r"(a[0]), "r"(a[1]), "r"(a[2]), "r"(a[3]), "r"(b[0]), "r"(b[1]));
}

// packed-u32 smem index: row m (0..127), u32-col c (0..15)
__device__ __forceinline__ int swz2(int m, int c) {
    return (m << 4) + ((c + (((m >> 1) & 3) << 2)) & 15);
}

// -------------------- grid barrier (single counter + epoch, tight poll) -------------
__device__ __forceinline__ void st_rel(unsigned* p, unsigned v) {
    asm volatile("st.release.gpu.u32 [%0], %1;" :: "l"(p), "r"(v) : "memory");
}
__device__ __forceinline__ unsigned ld_acq(const unsigned* p) {
    unsigned v;
    asm volatile("ld.acquire.gpu.u32 %0, [%1];" : "=r"(v) : "l"(p) : "memory");
    return v;
}
__device__ __forceinline__ void gbar(unsigned goal) {   // goal = absolute epoch
    __syncthreads();
    if (threadIdx.x == 0) {
        unsigned v;
        asm volatile("atom.add.acq_rel.gpu.u32 %0, [%1], %2;"
                     : "=r"(v) : "l"(&g_ctr), "r"(1u) : "memory");
        if (v + 1 == goal * NBLK) st_rel(&g_epoch, goal);
        while (ld_acq(&g_epoch) < goal) { }   // tight poll
    }
    __syncthreads();
}

// -------------------- reductions (512 threads = 16 warps) ---------------------------
__device__ __forceinline__ float warpMax(float v) {
    #pragma unroll
    for (int o = 16; o; o >>= 1) v = fmaxf(v, __shfl_xor_sync(0xffffffffu, v, o));
    return v;
}
__device__ __forceinline__ float warpSum(float v) {
    #pragma unroll
    for (int o = 16; o; o >>= 1) v += __shfl_xor_sync(0xffffffffu, v, o);
    return v;
}
__device__ float blockMax(float v, float* red) {
    v = warpMax(v);
    if ((threadIdx.x & 31) == 0) red[threadIdx.x >> 5] = v;
    __syncthreads();
    if (threadIdx.x < 32) {
        float x = (threadIdx.x < 16) ? red[threadIdx.x] : -3.4e38f;
        x = warpMax(x);
        if (threadIdx.x == 0) red[0] = x;
    }
    __syncthreads();
    float r = red[0];
    __syncthreads();
    return r;
}
__device__ float blockSum(float v, float* red) {
    v = warpSum(v);
    if ((threadIdx.x & 31) == 0) red[threadIdx.x >> 5] = v;
    __syncthreads();
    if (threadIdx.x < 32) {
        float x = (threadIdx.x < 16) ? red[threadIdx.x] : 0.f;
        x = warpSum(x);
        if (threadIdx.x == 0) red[0] = x;
    }
    __syncthreads();
    float r = red[0];
    __syncthreads();
    return r;
}

// -------------------- one-time weight hi/lo split + bf16x2 pack ----------------------
// src row stride = srcld; copy `cols` columns starting at src (pointer pre-offset)
__device__ void split_seg(size_t dbase, int dld, int dcol,
                          const float* __restrict__ src, int srcld, int rows, int cols)
{
    const int gid = blockIdx.x * NTHR + threadIdx.x;
    const int total = (rows * cols) >> 2;
    const int c4 = cols >> 2;
    for (int i = gid; i < total; i += NBLK * NTHR) {
        const int r = i / c4;
        const int c = (i - r * c4) << 2;
        const float4 v = *reinterpret_cast<const float4*>(src + (size_t)r * srcld + c);
        const unsigned h0 = pbf2(v.x, v.y);
        const unsigned h1 = pbf2(v.z, v.w);
        const unsigned l0 = pbf2(v.x - bflo(h0), v.y - bfhi(h0));
        const unsigned l1 = pbf2(v.z - bflo(h1), v.w - bfhi(h1));
        const size_t o2 = (dbase + (size_t)r * dld + dcol + c) >> 1;
        g_wh[o2] = h0; g_wh[o2 + 1] = h1;
        g_wl[o2] = l0; g_wl[o2 + 1] = l1;
    }
}

// -------------------- one-time emb-gate table: T[y][n] = emb[y] . Wih1[n, :512] -----
__device__ void etab_build(const float* __restrict__ emb, const float* __restrict__ Wih1)
{
    const int w = threadIdx.x >> 5, ln = threadIdx.x & 31;
    const int n = blockIdx.x * 16 + w;         // 128 blocks x 16 warps = 2048 rows
    const float* wr = Wih1 + (size_t)n * 640;  // cols 0..511 = emb part
    float wv[16];
    #pragma unroll
    for (int it = 0; it < 4; it++) {
        const float4 x = *reinterpret_cast<const float4*>(wr + it * 128 + ln * 4);
        wv[it * 4 + 0] = x.x; wv[it * 4 + 1] = x.y;
        wv[it * 4 + 2] = x.z; wv[it * 4 + 3] = x.w;
    }
    for (int y = 0; y < CC; y++) {
        const float* er = emb + (size_t)y * HID;
        float s = 0.f;
        #pragma unroll
        for (int it = 0; it < 4; it++) {
            const float4 e = *reinterpret_cast<const float4*>(er + it * 128 + ln * 4);
            s += wv[it * 4 + 0] * e.x + wv[it * 4 + 1] * e.y
               + wv[it * 4 + 2] * e.z + wv[it * 4 + 3] * e.w;
        }
        s = warpSum(s);
        if (ln == 0) g_etab[(size_t)y * 2048 + n] = s;
    }
}

// -------------------- tensor-core GEMM job (3xBF16 m16n8k16, 4x4 warps) --------------
__device__ void gemm_mma(SmemAll& SS, int jid, int t,
    float* part, int partN, int ntN, int nchunks, int ksplit,
    const float* p1, int l1, int s1,
    const float* p2, int l2,
    size_t woff, int wld)
{
    if (jid < 0 || jid >= ntN * ksplit) return;
    unsigned* AH = SS.g.ah; unsigned* AL = SS.g.al;
    unsigned* WH = SS.g.wh; unsigned* WL = SS.g.wl;

    const int tid = threadIdx.x;
    const int nt = jid / ksplit, ks = jid % ksplit;
    const int N0 = nt * 128;
    const int q = nchunks / ksplit, r = nchunks % ksplit;
    const int cnt = q + (ks < r ? 1 : 0);
    const int c0 = ks * q + (ks < r ? ks : r);

    const int lm  = tid & 127;
    const int lkg = (tid >> 7) << 3;
    const int lane = tid & 31;
    const int wid = tid >> 5;
    const int wm = wid & 3;
    const int wn = wid >> 2;
    const int fr = lane >> 2;
    const int fc = lane & 3;

    const unsigned* wsh2 = g_wh + (woff >> 1) + (size_t)(N0 + lm) * (wld >> 1);
    const unsigned* wsl2 = g_wl + (woff >> 1) + (size_t)(N0 + lm) * (wld >> 1);

    float acc[2][4][4];
    #pragma unroll
    for (int i = 0; i < 2; i++)
        #pragma unroll
        for (int j = 0; j < 4; j++)
            #pragma unroll
            for (int x = 0; x < 4; x++) acc[i][j][x] = 0.f;

    float4 ar0, ar1;
    uint4 w4h, w4l;

    #define LOADCHUNK(CK)                                                        \
        {                                                                        \
            const int gk = ((CK) << 5) + lkg;                                    \
            const float* ap;                                                     \
            if (gk < s1) ap = p1 + (size_t)lm * l1 + gk;                         \
            else         ap = p2 + (size_t)lm * l2 + (gk - s1);                  \
            ar0 = *reinterpret_cast<const float4*>(ap);                          \
            ar1 = *reinterpret_cast<const float4*>(ap + 4);                      \
            w4h = *reinterpret_cast<const uint4*>(wsh2 + (gk >> 1));             \
            w4l = *reinterpret_cast<const uint4*>(wsl2 + (gk >> 1));             \
        }

    LOADCHUNK(c0);

    const int c0u = (tid >> 7) << 2;
    const int dstg = (lm << 4) + ((c0u + (((lm >> 1) & 3) << 2)) & 15);

    for (int cc = 0; cc < cnt; cc++) {
        __syncthreads();
        {
            const unsigned h0 = pbf2(ar0.x, ar0.y);
            const unsigned h1 = pbf2(ar0.z, ar0.w);
            const unsigned h2 = pbf2(ar1.x, ar1.y);
            const unsigned h3 = pbf2(ar1.z, ar1.w);
            const unsigned l0 = pbf2(ar0.x - bflo(h0), ar0.y - bfhi(h0));
            const unsigned l1 = pbf2(ar0.z - bflo(h1), ar0.w - bfhi(h1));
            const unsigned l2r = pbf2(ar1.x - bflo(h2), ar1.y - bfhi(h2));
            const unsigned l3 = pbf2(ar1.z - bflo(h3), ar1.w - bfhi(h3));
            *reinterpret_cast<uint4*>(AH + dstg) = make_uint4(h0, h1, h2, h3);
            *reinterpret_cast<uint4*>(AL + dstg) = make_uint4(l0, l1, l2r, l3);
            *reinterpret_cast<uint4*>(WH + dstg) = w4h;
            *reinterpret_cast<uint4*>(WL + dstg) = w4l;
        }
        __syncthreads();

        if (cc + 1 < cnt) LOADCHUNK(c0 + cc + 1);

        #pragma unroll
        for (int ks2 = 0; ks2 < 2; ks2++) {
            const int kb2 = ks2 << 3;
            uint32_t ah[2][4], al[2][4];
            #pragma unroll
            for (int m2 = 0; m2 < 2; m2++) {
                const int ra = 32 * wm + 16 * m2 + fr;
                ah[m2][0] = AH[swz2(ra,     kb2 + fc)];
                ah[m2][1] = AH[swz2(ra + 8, kb2 + fc)];
                ah[m2][2] = AH[swz2(ra,     kb2 + fc + 4)];
                ah[m2][3] = AH[swz2(ra + 8, kb2 + fc + 4)];
                al[m2][0] = AL[swz2(ra,     kb2 + fc)];
                al[m2][1] = AL[swz2(ra + 8, kb2 + fc)];
                al[m2][2] = AL[swz2(ra,     kb2 + fc + 4)];
                al[m2][3] = AL[swz2(ra + 8, kb2 + fc + 4)];
            }
            #pragma unroll
            for (int j = 0; j < 4; j++) {
                const int nb = 32 * wn + 8 * j + fr;
                uint32_t bh[2], bl[2];
                bh[0] = WH[swz2(nb, kb2 + fc)];
                bh[1] = WH[swz2(nb, kb2 + fc + 4)];
                bl[0] = WL[swz2(nb, kb2 + fc)];
                bl[1] = WL[swz2(nb, kb2 + fc + 4)];
                mma16(acc[0][j], ah[0], bh);
                mma16(acc[0][j], ah[0], bl);
                mma16(acc[0][j], al[0], bh);
                mma16(acc[1][j], ah[1], bh);
                mma16(acc[1][j], ah[1], bl);
                mma16(acc[1][j], al[1], bh);
            }
        }
    }
    #undef LOADCHUNK

    #pragma unroll
    for (int m2 = 0; m2 < 2; m2++)
        #pragma unroll
        for (int j = 0; j < 4; j++) {
            const int row0 = 32 * wm + 16 * m2 + fr;
            const int col = N0 + 32 * wn + 8 * j + 2 * fc;
            float* op0 = part + (size_t)(ks * BATCH + row0) * partN + col;
            float* op1 = part + (size_t)(ks * BATCH + row0 + 8) * partN + col;
            *reinterpret_cast<float2*>(op0) = make_float2(acc[m2][j][0], acc[m2][j][1]);
            *reinterpret_cast<float2*>(op1) = make_float2(acc[m2][j][2], acc[m2][j][3]);
        }
}

// -------------------- LSTM pointwise update (block = batch row) ---------------------
// etab != nullptr: add per-class gate bias T[y][.] (LSTM1 emb contribution)
__device__ void update_phase(float* h, float* c, const float* bih, const float* bhh,
                             int nks, const float* etab)
{
    const int b = blockIdx.x;
    const int j = threadIdx.x;
    float gi = bih[j] + bhh[j];
    float gf = bih[j + 512] + bhh[j + 512];
    float gg = bih[j + 1024] + bhh[j + 1024];
    float go = bih[j + 1536] + bhh[j + 1536];
    if (etab) {
        gi += etab[j];
        gf += etab[j + 512];
        gg += etab[j + 1024];
        go += etab[j + 1536];
    }
    for (int ks = 0; ks < nks; ks++) {
        const float* pk = g_part + (size_t)(ks * BATCH + b) * 2048;
        gi += pk[j];
        gf += pk[j + 512];
        gg += pk[j + 1024];
        go += pk[j + 1536];
    }
    const float ig = sigm_f(gi);
    const float fg = sigm_f(gf);
    const float og = sigm_f(go);
    const float gv = tanh_f(gg);
    const int idx = b * HID + j;
    const float cn = fg * c[idx] + ig * gv;
    c[idx] = cn;
    h[idx] = og * tanh_f(cn);
}

// -------------------- fused (upd3 +) attention (block = batch row) ------------------
__device__ void attend_phase(SmemAll& SS, const float* key, const float* value,
                             const int* flens, const float* Wq, const float* bq,
                             const float* bih3, const float* bhh3, int fuse)
{
    AttSmem& A = SS.a;
    const int b = blockIdx.x;
    const int tid = threadIdx.x;

    if (fuse) {
        const int j = tid;
        float gi = bih3[j] + bhh3[j];
        float gf = bih3[j + 512] + bhh3[j + 512];
        float gg = bih3[j + 1024] + bhh3[j + 1024];
        float go = bih3[j + 1536] + bhh3[j + 1536];
        #pragma unroll
        for (int ks = 0; ks < 8; ks++) {
            const float* pk = g_part + (size_t)(ks * BATCH + b) * 2048;
            gi += pk[j];
            gf += pk[j + 512];
            gg += pk[j + 1024];
            go += pk[j + 1536];
        }
        const float ig = sigm_f(gi);
        const float fg = sigm_f(gf);
        const float og = sigm_f(go);
        const float gv = tanh_f(gg);
        const int idx = b * HID + j;
        const float cn = fg * g_c3[idx] + ig * gv;
        g_c3[idx] = cn;
        const float hn = og * tanh_f(cn);
        g_h3[idx] = hn;
        A.hs[j] = hn;
    } else {
        A.hs[tid] = g_h3[b * HID + tid];
    }
    __syncthreads();

    // q = h3 @ Wq^T + bq : warp w -> outputs a = 8w..8w+7, lanes split k (coalesced)
    {
        const int w = tid >> 5, ln = tid & 31;
        #pragma unroll
        for (int i = 0; i < 8; i++) {
            const int a = (w << 3) + i;
            const float* wr = Wq + (size_t)a * HID;
            float s = 0.f;
            #pragma unroll
            for (int it = 0; it < 4; it++) {
                const int k = it * 128 + ln * 4;
                const float4 wv = *reinterpret_cast<const float4*>(wr + k);
                s += wv.x * A.hs[k] + wv.y * A.hs[k + 1]
                   + wv.z * A.hs[k + 2] + wv.w * A.hs[k + 3];
            }
            s = warpSum(s);
            if (ln == 0) A.qs[a] = s + bq[a];
        }
    }
    __syncthreads();

    // energy: 2 threads per position t (64 a each) — coalesced over tp
    {
        const int tp = tid & 255;
        const int hf = tid >> 8;
        const float* kp = key + (size_t)b * ATT * TT + tp;
        float e = 0.f;
        #pragma unroll 8
        for (int a = 0; a < 64; a++) e += A.qs[hf * 64 + a] * kp[(size_t)(hf * 64 + a) * TT];
        A.pr[tid] = e;
    }
    __syncthreads();

    const int flen = flens[b] >> 3;
    const float ev = (tid < 256) ? (A.pr[tid] + A.pr[tid + 256]) : -3.4e38f;
    const float mx = blockMax(ev, A.red);
    const float w2 = (tid < 256 && tid < flen) ? __expf(ev - mx) : 0.f;
    const float sm = blockSum(w2, A.red);
    if (tid < 256) A.at[tid] = w2 / sm;
    __syncthreads();

    // ctx = attn @ value : 4 threads per output v (coalesced over v)
    {
        const int v = tid & 127;
        const int p = tid >> 7;
        const float* vp = value + (size_t)b * TT * ATT + (size_t)(p * 64) * ATT + v;
        float cs = 0.f;
        #pragma unroll 8
        for (int t2 = 0; t2 < 64; t2++) cs += A.at[p * 64 + t2] * vp[(size_t)t2 * ATT];
        A.pr[tid] = cs;
    }
    __syncthreads();
    if (tid < ATT)
        g_ctx[b * ATT + tid] = A.pr[tid] + A.pr[tid + 128] + A.pr[tid + 256] + A.pr[tid + 384];
    __syncthreads();
}

// -------------------- proj: 4 batch rows per block (blocks 0..31), coalesced --------
__device__ void proj_phase4(SmemAll& SS, const float* emb, const float* bproj,
                            const float* bmlp, float* out, int t, int ml, int pb)
{
    Proj4Smem& P = SS.p4;
    const int tid = threadIdx.x;

    for (int idx = tid; idx < 2048; idx += NTHR) {
        const int rr = idx >> 9, j = idx & 511;
        const int b = pb * 4 + rr;
        float s = bmlp[j];
        #pragma unroll
        for (int ks = 0; ks < 8; ks++)
            s += g_mpart[((size_t)(ks * BATCH) + b) * HID + j];
        P.ms[rr][j] = (s >= 0.f) ? s : NEG_SLOPE * s;
    }
    __syncthreads();

    // logits: warp w -> row rr = w>>2, 64 classes; lanes split k (coalesced LDG.128)
    {
        const int w = tid >> 5, ln = tid & 31;
        const int rr = w >> 2;
        const int cb = (w & 3) << 6;
        const float* mr = P.ms[rr];
        for (int j = 0; j < 64; j++) {
            const int c = cb + j;
            const float* er = emb + (size_t)c * HID;
            float s = 0.f;
            #pragma unroll
            for (int it = 0; it < 4; it++) {
                const int k = it * 128 + ln * 4;
                const float4 wv = *reinterpret_cast<const float4*>(er + k);
                s += wv.x * mr[k] + wv.y * mr[k + 1] + wv.z * mr[k + 2] + wv.w * mr[k + 3];
            }
            s = warpSum(s);
            if (ln == 0) P.lg[rr][c] = s + bproj[c];
        }
    }
    __syncthreads();

    // per-row log-softmax: 128 threads per row
    const int rr2 = tid >> 7;
    const int c2 = tid & 127;
    const int wq = (tid >> 5) & 3;
    const float v0 = P.lg[rr2][c2], v1 = P.lg[rr2][c2 + 128];
    float mx = warpMax(fmaxf(v0, v1));
    if ((tid & 31) == 0) P.red[rr2 * 4 + wq] = mx;
    __syncthreads();
    mx = fmaxf(fmaxf(P.red[rr2 * 4 + 0], P.red[rr2 * 4 + 1]),
               fmaxf(P.red[rr2 * 4 + 2], P.red[rr2 * 4 + 3]));
    float sm = warpSum(__expf(v0 - mx) + __expf(v1 - mx));
    if ((tid & 31) == 0) P.red[16 + rr2 * 4 + wq] = sm;
    __syncthreads();
    sm = P.red[16 + rr2 * 4 + 0] + P.red[16 + rr2 * 4 + 1]
       + P.red[16 + rr2 * 4 + 2] + P.red[16 + rr2 * 4 + 3];
    const float lsm = __logf(sm);
    const int b = pb * 4 + rr2;
    float* op = out + ((size_t)b * ml + t) * CC;
    op[c2]       = v0 - mx - lsm;
    op[c2 + 128] = v1 - mx - lsm;
    __syncthreads();
}

// -------------------- persistent megakernel -----------------------------------------
__global__ __launch_bounds__(NTHR, 1) void mega_kernel(
    const float* key, const float* value, const int* Yin, const int* flens,
    const float* emb, const float* Wq, const float* bq,
    const float* Wih1, const float* Whh1, const float* bih1, const float* bhh1,
    const float* Wih2, const float* Whh2, const float* bih2, const float* bhh2,
    const float* Wih3, const float* Whh3, const float* bih3, const float* bhh3,
    const float* Wmlp, const float* bmlp, const float* bproj,
    const float* h00, const float* h01, const float* h02,
    const float* c00, const float* c01, const float* c02,
    float* out, int ml, int ystride)
{
    extern __shared__ char dyn_smem[];
    char* sb = (char*)((((uintptr_t)dyn_smem) + 1023) & ~(uintptr_t)1023);
    SmemAll& S = *reinterpret_cast<SmemAll*>(sb);

    const int tid = threadIdx.x;
    const int bid = blockIdx.x;
    const unsigned base = ld_acq(&g_epoch);   // monotonic across replays
    unsigned bn = 0;

    // ---- one-time (per launch): weight hi/lo bf16 pre-split + emb-gate table ----
    split_seg(W1OFF, 640, 0,    Wih1 + 512, 640, 2048, 128);   // ctx part of Wih1
    split_seg(W1OFF, 640, 128,  Whh1, 512, 2048, 512);
    split_seg(W2OFF, W2LD, 0,   Wih2, 512, 2048, 512);
    split_seg(W2OFF, W2LD, 512, Whh2, 512, 2048, 512);
    split_seg(W3OFF, W3LD, 0,   Wih3, 512, 2048, 512);
    split_seg(W3OFF, W3LD, 512, Whh3, 512, 2048, 512);
    split_seg(WMOFF, WMLD, 0,   Wmlp, 640, 512, 640);
    etab_build(emb, Wih1);

    // init state (broadcast initial h/c); 128*512 threads == BATCH*HID
    {
        const int idx = bid * NTHR + tid;
        const int j = idx & 511;
        g_h1[idx] = h00[j]; g_h2[idx] = h01[j]; g_h3[idx] = h02[j];
        g_c1[idx] = c00[j]; g_c2[idx] = c01[j]; g_c3[idx] = c02[j];
    }
    gbar(base + ++bn);
    attend_phase(S, key, value, flens, Wq, bq, bih3, bhh3, 0);
    gbar(base + ++bn);

    for (int t = 0; t < ml; t++) {
        // P1: GEMM1(t): A=[ctx|h1], K=640 on blocks 0..95 (ksplit 6) || mlp(t-1)
        if (bid < 96) {
            gemm_mma(S, bid, t, g_part, 2048, 16, 20, 6,
                     g_ctx, ATT, 128, g_h1, HID,
                     W1OFF, W1LD);
        } else if (t > 0) {
            gemm_mma(S, bid - 96, t, g_mpart, 512, 4, 20, 8,
                     g_h3, HID, 512, g_ctx, ATT,
                     WMOFF, WMLD);
        }
        gbar(base + ++bn);

        // P2: upd1(t) (adds emb-gate table row) + coalesced proj4(t-1) on blocks 0..31
        update_phase(g_h1, g_c1, bih1, bhh1, 6,
                     g_etab + (size_t)Yin[blockIdx.x * ystride + t] * 2048);
        if (t > 0 && bid < 32)
            proj_phase4(S, emb, bproj, bmlp, out, t - 1, ml, bid);
        gbar(base + ++bn);

        // P3: LSTM2 gate GEMM: A = [h1 | h2], K=1024
        gemm_mma(S, bid, t, g_part, 2048, 16, 32, 8,
                 g_h1, HID, 512, g_h2, HID,
                 W2OFF, W2LD);
        gbar(base + ++bn);

        // P4: upd2
        update_phase(g_h2, g_c2, bih2, bhh2, 8, nullptr);
        gbar(base + ++bn);

        // P5: LSTM3 gate GEMM: A = [h2 | h3], K=1024
        gemm_mma(S, bid, t, g_part, 2048, 16, 32, 8,
                 g_h2, HID, 512, g_h3, HID,
                 W3OFF, W3LD);
        gbar(base + ++bn);

        // P6: attend(t) with fused upd3
        attend_phase(S, key, value, flens, Wq, bq, bih3, bhh3, 1);
        gbar(base + ++bn);
    }

    // drain: mlp(ml-1) then proj(ml-1)
    if (bid >= 96) {
        gemm_mma(S, bid - 96, ml - 1, g_mpart, 512, 4, 20, 8,
                 g_h3, HID, 512, g_ctx, ATT,
                 WMOFF, WMLD);
    }
    gbar(base + ++bn);
    if (bid < 32)
        proj_phase4(S, emb, bproj, bmlp, out, ml - 1, ml, bid);
}

// -------------------- launch ----------------------------------------------------------
extern "C" void kernel_launch(void* const* d_in, const int* in_sizes, int n_in,
                              void* d_out, int out_size)
{
    const float* key        = (const float*)d_in[0];
    const float* value      = (const float*)d_in[1];
    const int*   Yinput     = (const int*)d_in[2];
    const int*   frame_lens = (const int*)d_in[3];
    // d_in[4] = max_len scalar; derived from out_size instead
    const float* emb   = (const float*)d_in[5];
    const float* Wq    = (const float*)d_in[6];
    const float* bq    = (const float*)d_in[7];
    const float* Wih1  = (const float*)d_in[8];
    const float* Whh1  = (const float*)d_in[9];
    const float* bih1  = (const float*)d_in[10];
    const float* bhh1  = (const float*)d_in[11];
    const float* Wih2  = (const float*)d_in[12];
    const float* Whh2  = (const float*)d_in[13];
    const float* bih2  = (const float*)d_in[14];
    const float* bhh2  = (const float*)d_in[15];
    const float* Wih3  = (const float*)d_in[16];
    const float* Whh3  = (const float*)d_in[17];
    const float* bih3  = (const float*)d_in[18];
    const float* bhh3  = (const float*)d_in[19];
    const float* Wmlp  = (const float*)d_in[20];
    const float* bmlp  = (const float*)d_in[21];
    const float* bproj = (const float*)d_in[22];
    const float* h00 = (const float*)d_in[23];
    const float* h01 = (const float*)d_in[24];
    const float* h02 = (const float*)d_in[25];
    const float* c00 = (const float*)d_in[26];
    const float* c01 = (const float*)d_in[27];
    const float* c02 = (const float*)d_in[28];

    float* out = (float*)d_out;
    const int ml = out_size / (BATCH * CC);     // 300
    const int ystride = in_sizes[2] / BATCH;    // MAXLEN = 300

    cudaFuncSetAttribute(mega_kernel,
                         cudaFuncAttributeMaxDynamicSharedMemorySize, SMEM_BYTES);

    mega_kernel<<<NBLK, NTHR, SMEM_BYTES>>>(
        key, value, Yinput, frame_lens,
        emb, Wq, bq,
        Wih1, Whh1, bih1, bhh1,
        Wih2, Whh2, bih2, bhh2,
        Wih3, Whh3, bih3, bhh3,
        Wmlp, bmlp, bproj,
        h00, h01, h02, c00, c01, c02,
        out, ml, ystride);
}